// round 1
// baseline (speedup 1.0000x reference)
#include <cuda_runtime.h>

// Problem constants (fixed by setup_inputs): B=2, t=5, C=16, G=64
#define G 64
#define GG (G * G)           // 4096
#define GGG (G * G * G)      // 262144
#define NCH 16
#define CVOL (NCH * GGG)     // one (C,D,H,W) volume = 4,194,304 floats
#define NPAIR 8              // B*(t-1)

// Per-pair fused affine map from integer output indices (x,y,z) to fractional
// sample coordinates (fx,fy,fz):
//   f_i = M[i*4+0]*x + M[i*4+1]*y + M[i*4+2]*z + M[i*4+3]
__device__ float g_M[NPAIR][12];

__global__ void xform_kernel(const float* __restrict__ poses /* (2,5,4,4) */) {
    int n = threadIdx.x;
    if (n >= NPAIR) return;
    int b = n >> 2;
    int k = (n & 3) + 1;  // frame index 1..4
    const float* P0 = poses + (size_t)(b * 5 + 0) * 16;
    const float* P1 = poses + (size_t)(b * 5 + k) * 16;

    // T = P0 @ inv(P1); P1 rigid => inv(P1) = [R1^T | -R1^T t1]
    // R = R0 @ R1^T ; t = t0 - R @ t1
    float R[3][3], t[3];
#pragma unroll
    for (int i = 0; i < 3; i++)
#pragma unroll
        for (int j = 0; j < 3; j++)
            R[i][j] = P0[i * 4 + 0] * P1[j * 4 + 0]
                    + P0[i * 4 + 1] * P1[j * 4 + 1]
                    + P0[i * 4 + 2] * P1[j * 4 + 2];
#pragma unroll
    for (int i = 0; i < 3; i++)
        t[i] = P0[i * 4 + 3]
             - (R[i][0] * P1[3] + R[i][1] * P1[7] + R[i][2] * P1[11]);

    // m = (G-1)/2 * (1/G) = 63/128
    // grid point p_j = m * (2*k_j - 63)/63, sample s_i = cam_i/m,
    // pixel coord f_i = ((s_i + 1)*G - 1)*0.5 = 32*s_i + 31.5
    //  => f_i = (64/63) * sum_j R[i][j]*k_j
    //           + 32*( t_i*(128/63) - (R[i][0]+R[i][1]+R[i][2]) ) + 31.5
    const float inv_m = 128.0f / 63.0f;
    const float s = 64.0f / 63.0f;
#pragma unroll
    for (int i = 0; i < 3; i++) {
        g_M[n][i * 4 + 0] = s * R[i][0];
        g_M[n][i * 4 + 1] = s * R[i][1];
        g_M[n][i * 4 + 2] = s * R[i][2];
        g_M[n][i * 4 + 3] =
            32.0f * (t[i] * inv_m - (R[i][0] + R[i][1] + R[i][2])) + 31.5f;
    }
}

__global__ __launch_bounds__(256) void warp_kernel(const float* __restrict__ vox,
                                                   float* __restrict__ out) {
    const int x = threadIdx.x;                       // 0..63
    const int y = (blockIdx.x << 2) | threadIdx.y;   // 0..63
    const int z = blockIdx.y;                        // 0..63
    const int n = blockIdx.z;                        // 0..7

    __shared__ float Ms[12];
    if (threadIdx.y == 0 && threadIdx.x < 12) Ms[threadIdx.x] = g_M[n][threadIdx.x];
    __syncthreads();

    const float xf_ = (float)x, yf_ = (float)y, zf_ = (float)z;
    float fx = fmaf(Ms[2], zf_, fmaf(Ms[1], yf_, fmaf(Ms[0], xf_, Ms[3])));
    float fy = fmaf(Ms[6], zf_, fmaf(Ms[5], yf_, fmaf(Ms[4], xf_, Ms[7])));
    float fz = fmaf(Ms[10], zf_, fmaf(Ms[9], yf_, fmaf(Ms[8], xf_, Ms[11])));

    float xfl = floorf(fx), yfl = floorf(fy), zfl = floorf(fz);
    float tx = fx - xfl, ty = fy - yfl, tz = fz - zfl;
    int ix0 = (int)xfl, iy0 = (int)yfl, iz0 = (int)zfl;

    // per-axis weights with zero-padding validity folded in
    float wx0 = ((unsigned)ix0 < (unsigned)G) ? (1.0f - tx) : 0.0f;
    float wx1 = ((unsigned)(ix0 + 1) < (unsigned)G) ? tx : 0.0f;
    float wy0 = ((unsigned)iy0 < (unsigned)G) ? (1.0f - ty) : 0.0f;
    float wy1 = ((unsigned)(iy0 + 1) < (unsigned)G) ? ty : 0.0f;
    float wz0 = ((unsigned)iz0 < (unsigned)G) ? (1.0f - tz) : 0.0f;
    float wz1 = ((unsigned)(iz0 + 1) < (unsigned)G) ? tz : 0.0f;

    // clamped indices (safe addresses even when weight == 0)
    int xc0 = max(0, min(ix0, G - 1)),     xc1 = max(0, min(ix0 + 1, G - 1));
    int yc0 = max(0, min(iy0, G - 1)),     yc1 = max(0, min(iy0 + 1, G - 1));
    int zc0 = max(0, min(iz0, G - 1)),     zc1 = max(0, min(iz0 + 1, G - 1));

    int oz0 = zc0 * GG, oz1 = zc1 * GG;
    int oy0 = yc0 * G,  oy1 = yc1 * G;

    int o000 = oz0 + oy0 + xc0, o001 = oz0 + oy0 + xc1;
    int o010 = oz0 + oy1 + xc0, o011 = oz0 + oy1 + xc1;
    int o100 = oz1 + oy0 + xc0, o101 = oz1 + oy0 + xc1;
    int o110 = oz1 + oy1 + xc0, o111 = oz1 + oy1 + xc1;

    float wz0y0 = wz0 * wy0, wz0y1 = wz0 * wy1;
    float wz1y0 = wz1 * wy0, wz1y1 = wz1 * wy1;
    float w000 = wz0y0 * wx0, w001 = wz0y0 * wx1;
    float w010 = wz0y1 * wx0, w011 = wz0y1 * wx1;
    float w100 = wz1y0 * wx0, w101 = wz1y0 * wx1;
    float w110 = wz1y1 * wx0, w111 = wz1y1 * wx1;

    const int b = n >> 2;
    const int k = n & 3;
    const int frame = b * 5 + 1 + k;                 // index into (B*t) frames
    const float* src = vox + (size_t)frame * CVOL;
    float* dst = out + (size_t)frame * CVOL + (z * GG + y * G + x);

#pragma unroll 4
    for (int c = 0; c < NCH; c++) {
        const float* v = src + c * GGG;
        float acc;
        acc = w000 * __ldg(v + o000);
        acc = fmaf(w001, __ldg(v + o001), acc);
        acc = fmaf(w010, __ldg(v + o010), acc);
        acc = fmaf(w011, __ldg(v + o011), acc);
        acc = fmaf(w100, __ldg(v + o100), acc);
        acc = fmaf(w101, __ldg(v + o101), acc);
        acc = fmaf(w110, __ldg(v + o110), acc);
        acc = fmaf(w111, __ldg(v + o111), acc);
        dst[c * GGG] = acc;
    }
}

extern "C" void kernel_launch(void* const* d_in, const int* in_sizes, int n_in,
                              void* d_out, int out_size) {
    const float* vox   = (const float*)d_in[0];   // (2,5,16,64,64,64) fp32
    const float* poses = (const float*)d_in[1];   // (2,5,4,4) fp32
    float* out = (float*)d_out;

    // 1) per-pair affine transforms
    xform_kernel<<<1, 32>>>(poses);

    // 2) copy frame 0 of each batch: out[b,0] = voxels[b,0]
    const size_t frameBytes = (size_t)CVOL * sizeof(float);
    cudaMemcpyAsync(out, vox, frameBytes, cudaMemcpyDeviceToDevice);
    cudaMemcpyAsync(out + (size_t)5 * CVOL, vox + (size_t)5 * CVOL, frameBytes,
                    cudaMemcpyDeviceToDevice);

    // 3) warp frames 1..4 of each batch
    dim3 block(64, 4, 1);        // x full row, 4 y rows -> 256 threads
    dim3 grid(G / 4, G, NPAIR);  // (y tiles, z, pair)
    warp_kernel<<<grid, block>>>(vox, out);
}

// round 2
// speedup vs baseline: 2.0383x; 2.0383x over previous
#include <cuda_runtime.h>

// Problem constants (fixed by setup_inputs): B=2, t=5, C=16, G=64
#define G 64
#define GG 4096
#define GGG 262144
#define NCH 16
#define CVOL (NCH * GGG)   // 4,194,304 floats per (C,D,H,W) frame
#define NPAIR 8
#define PITCH 17           // smem x pitch (16 + 1 pad)
#define ZSTRIDE (16 * PITCH)  // 272 floats per smem z-plane

// Per-pair fused affine map: f_i = M[i*4+0]*x + M[i*4+1]*y + M[i*4+2]*z + M[i*4+3]
__device__ float g_M[NPAIR][12];

__global__ void xform_kernel(const float* __restrict__ poses /* (2,5,4,4) */) {
    int n = threadIdx.x;
    if (n >= NPAIR) return;
    int b = n >> 2;
    int k = (n & 3) + 1;
    const float* P0 = poses + (size_t)(b * 5 + 0) * 16;
    const float* P1 = poses + (size_t)(b * 5 + k) * 16;

    // T = P0 @ inv(P1); P1 rigid => inv(P1) = [R1^T | -R1^T t1]
    float R[3][3], t[3];
#pragma unroll
    for (int i = 0; i < 3; i++)
#pragma unroll
        for (int j = 0; j < 3; j++)
            R[i][j] = P0[i * 4 + 0] * P1[j * 4 + 0]
                    + P0[i * 4 + 1] * P1[j * 4 + 1]
                    + P0[i * 4 + 2] * P1[j * 4 + 2];
#pragma unroll
    for (int i = 0; i < 3; i++)
        t[i] = P0[i * 4 + 3]
             - (R[i][0] * P1[3] + R[i][1] * P1[7] + R[i][2] * P1[11]);

    const float inv_m = 128.0f / 63.0f;
    const float s = 64.0f / 63.0f;
#pragma unroll
    for (int i = 0; i < 3; i++) {
        g_M[n][i * 4 + 0] = s * R[i][0];
        g_M[n][i * 4 + 1] = s * R[i][1];
        g_M[n][i * 4 + 2] = s * R[i][2];
        g_M[n][i * 4 + 3] =
            32.0f * (t[i] * inv_m - (R[i][0] + R[i][1] + R[i][2])) + 31.5f;
    }
}

// One block = one 8x8x8 output tile of one (batch,frame) pair.
// 256 threads; each thread handles 2 output points (z and z+4).
// Per channel: stage the tile's source AABB (<=16^3 guaranteed) into smem,
// then sample 8 corners from smem with constant offsets.
__global__ __launch_bounds__(256) void warp_kernel(const float* __restrict__ vox,
                                                   float* __restrict__ out) {
    const int tid = threadIdx.x;
    const int n = blockIdx.z >> 3;  // pair 0..7

    __shared__ float Ms[12];
    __shared__ int sO[3], sD[3];
    __shared__ int sSkip;
    __shared__ float tile[16 * ZSTRIDE];  // 4352 floats = 17.4 KB

    if (tid < 12) Ms[tid] = g_M[n][tid];
    __syncthreads();

    const int bx0 = (int)blockIdx.x * 8;
    const int by0 = (int)blockIdx.y * 8;
    const int bz0 = (int)(blockIdx.z & 7) * 8;

    if (tid == 0) {
        int skip = 0;
#pragma unroll
        for (int i = 0; i < 3; i++) {
            float a = Ms[i * 4 + 0], b = Ms[i * 4 + 1], c = Ms[i * 4 + 2], d = Ms[i * 4 + 3];
            float xl = (float)bx0, xh = (float)(bx0 + 7);
            float yl = (float)by0, yh = (float)(by0 + 7);
            float zl = (float)bz0, zh = (float)(bz0 + 7);
            float fmin = d + fminf(a * xl, a * xh) + fminf(b * yl, b * yh) + fminf(c * zl, c * zh);
            float fmax = d + fmaxf(a * xl, a * xh) + fmaxf(b * yl, b * yh) + fmaxf(c * zl, c * zh);
            int o = (int)floorf(fmin);
            int dd = (int)floorf(fmax) + 2 - o;  // covers floor..floor(max)+1
            if (dd > 16) dd = 16;                // mathematically <=15; safety
            sO[i] = o;
            sD[i] = dd;
            skip |= (o > 63) | (o + dd <= 0);
        }
        sSkip = skip;
    }
    __syncthreads();

    const int b = n >> 2, k = n & 3;
    const int frame = b * 5 + 1 + k;
    const float* __restrict__ src = vox + (size_t)frame * CVOL;
    float* __restrict__ dstf = out + (size_t)frame * CVOL;

    const int lx = bx0 + (tid & 7);
    const int ly = by0 + ((tid >> 3) & 7);
    const int lz = bz0 + (tid >> 6);  // p=0 z; p=1 adds 4
    const int dst0 = lz * GG + ly * G + lx;

    if (sSkip) {
#pragma unroll
        for (int c = 0; c < NCH; c++) {
            dstf[dst0 + c * GGG] = 0.0f;
            dstf[dst0 + 4 * GG + c * GGG] = 0.0f;
        }
        return;
    }

    const int ox = sO[0], oy = sO[1], oz = sO[2];
    const int dx = sD[0], dy = sD[1], dz = sD[2];

    // ---- per-point weights & smem base offsets (computed ONCE, reused over 16 ch)
    float w[2][8];
    int soff[2];
#pragma unroll
    for (int p = 0; p < 2; p++) {
        float xf = (float)lx, yf = (float)ly, zf = (float)(lz + p * 4);
        float fx = fmaf(Ms[2], zf, fmaf(Ms[1], yf, fmaf(Ms[0], xf, Ms[3])));
        float fy = fmaf(Ms[6], zf, fmaf(Ms[5], yf, fmaf(Ms[4], xf, Ms[7])));
        float fz = fmaf(Ms[10], zf, fmaf(Ms[9], yf, fmaf(Ms[8], xf, Ms[11])));
        float xfl = floorf(fx), yfl = floorf(fy), zfl = floorf(fz);
        float tx = fx - xfl, ty = fy - yfl, tz = fz - zfl;
        int ix0 = (int)xfl, iy0 = (int)yfl, iz0 = (int)zfl;

        float wx0 = ((unsigned)ix0 < 64u) ? (1.0f - tx) : 0.0f;
        float wx1 = ((unsigned)(ix0 + 1) < 64u) ? tx : 0.0f;
        float wy0 = ((unsigned)iy0 < 64u) ? (1.0f - ty) : 0.0f;
        float wy1 = ((unsigned)(iy0 + 1) < 64u) ? ty : 0.0f;
        float wz0 = ((unsigned)iz0 < 64u) ? (1.0f - tz) : 0.0f;
        float wz1 = ((unsigned)(iz0 + 1) < 64u) ? tz : 0.0f;

        float wz0y0 = wz0 * wy0, wz0y1 = wz0 * wy1;
        float wz1y0 = wz1 * wy0, wz1y1 = wz1 * wy1;
        w[p][0] = wz0y0 * wx0; w[p][1] = wz0y0 * wx1;
        w[p][2] = wz0y1 * wx0; w[p][3] = wz0y1 * wx1;
        w[p][4] = wz1y0 * wx0; w[p][5] = wz1y0 * wx1;
        w[p][6] = wz1y1 * wx0; w[p][7] = wz1y1 * wx1;

        // AABB origin is the raw floor(min); all corner indices land inside it.
        soff[p] = ((iz0 - oz) * 16 + (iy0 - oy)) * PITCH + (ix0 - ox);
    }

    // ---- cooperative loader setup: group (tid>>4) = y-row, lane (tid&15) = x
    const int grp = tid >> 4;
    const int xr = tid & 15;
    const bool active = (grp < dy) & (xr < dx);
    const int gxc = min(max(ox + xr, 0), 63);
    const int gyc = min(max(oy + grp, 0), 63);
    const int rowoff = gyc * G + gxc;     // clamped (y,x) source offset
    const int sts0 = grp * PITCH + xr;

#pragma unroll 1
    for (int c = 0; c < NCH; c++) {
        const float* __restrict__ sc = src + c * GGG;
        __syncthreads();  // previous channel's readers done
        if (active) {
            for (int i = 0; i < dz; i++) {
                int gzc = min(max(oz + i, 0), 63);
                tile[sts0 + i * ZSTRIDE] = __ldg(sc + (gzc * GG + rowoff));
            }
        }
        __syncthreads();

#pragma unroll
        for (int p = 0; p < 2; p++) {
            const int s = soff[p];
            float acc = w[p][0] * tile[s];
            acc = fmaf(w[p][1], tile[s + 1], acc);
            acc = fmaf(w[p][2], tile[s + PITCH], acc);
            acc = fmaf(w[p][3], tile[s + PITCH + 1], acc);
            acc = fmaf(w[p][4], tile[s + ZSTRIDE], acc);
            acc = fmaf(w[p][5], tile[s + ZSTRIDE + 1], acc);
            acc = fmaf(w[p][6], tile[s + ZSTRIDE + PITCH], acc);
            acc = fmaf(w[p][7], tile[s + ZSTRIDE + PITCH + 1], acc);
            dstf[dst0 + p * (4 * GG) + c * GGG] = acc;
        }
    }
}

extern "C" void kernel_launch(void* const* d_in, const int* in_sizes, int n_in,
                              void* d_out, int out_size) {
    const float* vox   = (const float*)d_in[0];   // (2,5,16,64,64,64) fp32
    const float* poses = (const float*)d_in[1];   // (2,5,4,4) fp32
    float* out = (float*)d_out;

    xform_kernel<<<1, 32>>>(poses);

    // copy frame 0 of each batch
    const size_t frameBytes = (size_t)CVOL * sizeof(float);
    cudaMemcpyAsync(out, vox, frameBytes, cudaMemcpyDeviceToDevice);
    cudaMemcpyAsync(out + (size_t)5 * CVOL, vox + (size_t)5 * CVOL, frameBytes,
                    cudaMemcpyDeviceToDevice);

    // 8x8x8 tiles: grid (8,8, 8 z-tiles * 8 pairs)
    dim3 block(256, 1, 1);
    dim3 grid(8, 8, 64);
    warp_kernel<<<grid, block>>>(vox, out);
}

// round 4
// speedup vs baseline: 2.0570x; 1.0092x over previous
#include <cuda_runtime.h>

// Problem constants (fixed by setup_inputs): B=2, t=5, C=16, G=64
#define G 64
#define GG 4096
#define GGG 262144
#define NCH 16
#define CVOL (NCH * GGG)   // 4,194,304 floats per (C,D,H,W) frame
#define NPAIR 8

// smem tile: 16 z-planes x 16 y-rows x 20 x-floats (x window 4-aligned)
#define XPITCH 20
#define YROWS 16
#define ZSTRIDE (YROWS * XPITCH)   // 320
#define TILE_FLOATS (16 * ZSTRIDE) // 5120 = 20.5 KB

// Per-pair fused affine map: f_i = M[i*4+0]*x + M[i*4+1]*y + M[i*4+2]*z + M[i*4+3]
__device__ float g_M[NPAIR][12];

__global__ void xform_kernel(const float* __restrict__ poses /* (2,5,4,4) */) {
    int n = threadIdx.x;
    if (n >= NPAIR) return;
    int b = n >> 2;
    int k = (n & 3) + 1;
    const float* P0 = poses + (size_t)(b * 5 + 0) * 16;
    const float* P1 = poses + (size_t)(b * 5 + k) * 16;

    // T = P0 @ inv(P1); P1 rigid => inv(P1) = [R1^T | -R1^T t1]
    float R[3][3], t[3];
#pragma unroll
    for (int i = 0; i < 3; i++)
#pragma unroll
        for (int j = 0; j < 3; j++)
            R[i][j] = P0[i * 4 + 0] * P1[j * 4 + 0]
                    + P0[i * 4 + 1] * P1[j * 4 + 1]
                    + P0[i * 4 + 2] * P1[j * 4 + 2];
#pragma unroll
    for (int i = 0; i < 3; i++)
        t[i] = P0[i * 4 + 3]
             - (R[i][0] * P1[3] + R[i][1] * P1[7] + R[i][2] * P1[11]);

    const float inv_m = 128.0f / 63.0f;
    const float s = 64.0f / 63.0f;
#pragma unroll
    for (int i = 0; i < 3; i++) {
        g_M[n][i * 4 + 0] = s * R[i][0];
        g_M[n][i * 4 + 1] = s * R[i][1];
        g_M[n][i * 4 + 2] = s * R[i][2];
        g_M[n][i * 4 + 3] =
            32.0f * (t[i] * inv_m - (R[i][0] + R[i][1] + R[i][2])) + 31.5f;
    }
}

// One block = one 8x8x8 output tile of one (batch,frame) pair. 256 threads,
// 2 output points each. Per channel: stage the source AABB with float4
// LDG/STS (addresses precomputed, channel-invariant), then 8-corner LDS.
__global__ __launch_bounds__(256) void warp_kernel(const float* __restrict__ vox,
                                                   float* __restrict__ out) {
    const int tid = threadIdx.x;
    const int n = blockIdx.z >> 3;  // pair 0..7

    __shared__ float Ms[12];
    __shared__ int sO[3], sD[3];
    __shared__ int sSkip;
    __shared__ __align__(16) float tile[TILE_FLOATS];

    if (tid < 12) Ms[tid] = g_M[n][tid];
    __syncthreads();

    const int bx0 = (int)blockIdx.x * 8;
    const int by0 = (int)blockIdx.y * 8;
    const int bz0 = (int)(blockIdx.z & 7) * 8;

    if (tid == 0) {
        int skip = 0;
#pragma unroll
        for (int i = 0; i < 3; i++) {
            float a = Ms[i * 4 + 0], b = Ms[i * 4 + 1], c = Ms[i * 4 + 2], d = Ms[i * 4 + 3];
            float xl = (float)bx0, xh = (float)(bx0 + 7);
            float yl = (float)by0, yh = (float)(by0 + 7);
            float zl = (float)bz0, zh = (float)(bz0 + 7);
            float fmin = d + fminf(a * xl, a * xh) + fminf(b * yl, b * yh) + fminf(c * zl, c * zh);
            float fmax = d + fmaxf(a * xl, a * xh) + fmaxf(b * yl, b * yh) + fmaxf(c * zl, c * zh);
            int o = (int)floorf(fmin);
            int dd = (int)floorf(fmax) + 2 - o;  // covers floor(min)..floor(max)+1 (<=15)
            if (dd > 16) dd = 16;                // safety
            sO[i] = o;
            sD[i] = dd;
            skip |= (o > 63) | (o + dd <= 0);
        }
        sSkip = skip;
    }
    __syncthreads();

    const int b = n >> 2, k = n & 3;
    const int frame = b * 5 + 1 + k;
    const float* __restrict__ src = vox + (size_t)frame * CVOL;
    float* __restrict__ dstf = out + (size_t)frame * CVOL;

    const int lx = bx0 + (tid & 7);
    const int ly = by0 + ((tid >> 3) & 7);
    const int lz = bz0 + (tid >> 6);  // p=0: z, p=1: z+4
    const int dst0 = lz * GG + ly * G + lx;

    if (sSkip) {
#pragma unroll
        for (int c = 0; c < NCH; c++) {
            dstf[dst0 + c * GGG] = 0.0f;
            dstf[dst0 + 4 * GG + c * GGG] = 0.0f;
        }
        return;
    }

    const int ox = sO[0], oy = sO[1], oz = sO[2];
    const int dz = sD[2];
    const int ox4 = ox & ~3;  // 4-aligned x window base

    // ---- per-point weights & smem base offsets (computed ONCE, reused over 16 ch)
    float w[2][8];
    int soff[2];
#pragma unroll
    for (int p = 0; p < 2; p++) {
        float xf = (float)lx, yf = (float)ly, zf = (float)(lz + p * 4);
        float fx = fmaf(Ms[2], zf, fmaf(Ms[1], yf, fmaf(Ms[0], xf, Ms[3])));
        float fy = fmaf(Ms[6], zf, fmaf(Ms[5], yf, fmaf(Ms[4], xf, Ms[7])));
        float fz = fmaf(Ms[10], zf, fmaf(Ms[9], yf, fmaf(Ms[8], xf, Ms[11])));
        float xfl = floorf(fx), yfl = floorf(fy), zfl = floorf(fz);
        float tx = fx - xfl, ty = fy - yfl, tz = fz - zfl;
        int ix0 = (int)xfl, iy0 = (int)yfl, iz0 = (int)zfl;

        float wx0 = ((unsigned)ix0 < 64u) ? (1.0f - tx) : 0.0f;
        float wx1 = ((unsigned)(ix0 + 1) < 64u) ? tx : 0.0f;
        float wy0 = ((unsigned)iy0 < 64u) ? (1.0f - ty) : 0.0f;
        float wy1 = ((unsigned)(iy0 + 1) < 64u) ? ty : 0.0f;
        float wz0 = ((unsigned)iz0 < 64u) ? (1.0f - tz) : 0.0f;
        float wz1 = ((unsigned)(iz0 + 1) < 64u) ? tz : 0.0f;

        float wz0y0 = wz0 * wy0, wz0y1 = wz0 * wy1;
        float wz1y0 = wz1 * wy0, wz1y1 = wz1 * wy1;
        w[p][0] = wz0y0 * wx0; w[p][1] = wz0y0 * wx1;
        w[p][2] = wz0y1 * wx0; w[p][3] = wz0y1 * wx1;
        w[p][4] = wz1y0 * wx0; w[p][5] = wz1y0 * wx1;
        w[p][6] = wz1y1 * wx0; w[p][7] = wz1y1 * wx1;

        soff[p] = ((iz0 - oz) * YROWS + (iy0 - oy)) * XPITCH + (ix0 - ox4);
    }

    // ---- precompute staging addresses (channel-invariant): dz*16 rows x 5 float4
    // Each float4 segment is 4-aligned in x -> fully in-range-x or fully OOB-x.
    // OOB-x / OOB-y / OOB-z segments carry zero weight; only address safety
    // needed -> clamp y,z to [0,63] and linear offset to [0, GGG-4]
    // (all candidates are multiples of 4, so alignment is preserved).
    int lin[5], sof[5];
    bool act[5];
    const int total = dz * 80;  // 16 y-rows * 5 segments per z-plane
#pragma unroll
    for (int i = 0; i < 5; i++) {
        int idx = tid + i * 256;
        act[i] = idx < total;
        int zi = idx / 80;
        int r = idx - zi * 80;
        int yi = r / 5;
        int s = r - yi * 5;
        int zc = min(max(oz + zi, 0), 63);
        int yc = min(max(oy + yi, 0), 63);
        int l = zc * GG + yc * G + (ox4 + 4 * s);
        lin[i] = min(max(l, 0), GGG - 4);
        sof[i] = zi * ZSTRIDE + yi * XPITCH + 4 * s;
    }

#pragma unroll 1
    for (int c = 0; c < NCH; c++) {
        const float* __restrict__ sc = src + c * GGG;
        __syncthreads();  // previous channel's readers done
#pragma unroll
        for (int i = 0; i < 5; i++) {
            if (act[i]) {
                float4 v = __ldg((const float4*)(sc + lin[i]));
                *(float4*)&tile[sof[i]] = v;
            }
        }
        __syncthreads();

#pragma unroll
        for (int p = 0; p < 2; p++) {
            const int s = soff[p];
            float acc = w[p][0] * tile[s];
            acc = fmaf(w[p][1], tile[s + 1], acc);
            acc = fmaf(w[p][2], tile[s + XPITCH], acc);
            acc = fmaf(w[p][3], tile[s + XPITCH + 1], acc);
            acc = fmaf(w[p][4], tile[s + ZSTRIDE], acc);
            acc = fmaf(w[p][5], tile[s + ZSTRIDE + 1], acc);
            acc = fmaf(w[p][6], tile[s + ZSTRIDE + XPITCH], acc);
            acc = fmaf(w[p][7], tile[s + ZSTRIDE + XPITCH + 1], acc);
            dstf[dst0 + p * (4 * GG) + c * GGG] = acc;
        }
    }
}

extern "C" void kernel_launch(void* const* d_in, const int* in_sizes, int n_in,
                              void* d_out, int out_size) {
    const float* vox   = (const float*)d_in[0];   // (2,5,16,64,64,64) fp32
    const float* poses = (const float*)d_in[1];   // (2,5,4,4) fp32
    float* out = (float*)d_out;

    xform_kernel<<<1, 32>>>(poses);

    // copy frame 0 of each batch
    const size_t frameBytes = (size_t)CVOL * sizeof(float);
    cudaMemcpyAsync(out, vox, frameBytes, cudaMemcpyDeviceToDevice);
    cudaMemcpyAsync(out + (size_t)5 * CVOL, vox + (size_t)5 * CVOL, frameBytes,
                    cudaMemcpyDeviceToDevice);

    // 8x8x8 tiles: grid (8,8, 8 z-tiles * 8 pairs)
    dim3 block(256, 1, 1);
    dim3 grid(8, 8, 64);
    warp_kernel<<<grid, block>>>(vox, out);
}

// round 5
// speedup vs baseline: 2.7295x; 1.3269x over previous
#include <cuda_runtime.h>

// Problem constants (fixed by setup_inputs): B=2, t=5, C=16, G=64
#define G 64
#define GG 4096
#define GGG 262144
#define NCH 16
#define CVOL (NCH * GGG)   // 4,194,304 floats per (C,D,H,W) frame
#define NPAIR 8

// smem tile: up to 16 z-planes x 16 y-rows x 20 x-floats (x window 4-aligned)
// z-plane stride padded to 324 (mod 32 = 4) to break z-neighbor bank collisions
#define XPITCH 20
#define ZSTRIDE 324
#define TILE_FLOATS (16 * ZSTRIDE)  // 5184 floats = 20.7 KB

// Per-pair fused affine map: f_i = M[i*4+0]*x + M[i*4+1]*y + M[i*4+2]*z + M[i*4+3]
__device__ float g_M[NPAIR][12];

__global__ void xform_kernel(const float* __restrict__ poses /* (2,5,4,4) */) {
    int n = threadIdx.x;
    if (n >= NPAIR) return;
    int b = n >> 2;
    int k = (n & 3) + 1;
    const float* P0 = poses + (size_t)(b * 5 + 0) * 16;
    const float* P1 = poses + (size_t)(b * 5 + k) * 16;

    // T = P0 @ inv(P1); P1 rigid => inv(P1) = [R1^T | -R1^T t1]
    float R[3][3], t[3];
#pragma unroll
    for (int i = 0; i < 3; i++)
#pragma unroll
        for (int j = 0; j < 3; j++)
            R[i][j] = P0[i * 4 + 0] * P1[j * 4 + 0]
                    + P0[i * 4 + 1] * P1[j * 4 + 1]
                    + P0[i * 4 + 2] * P1[j * 4 + 2];
#pragma unroll
    for (int i = 0; i < 3; i++)
        t[i] = P0[i * 4 + 3]
             - (R[i][0] * P1[3] + R[i][1] * P1[7] + R[i][2] * P1[11]);

    const float inv_m = 128.0f / 63.0f;
    const float s = 64.0f / 63.0f;
#pragma unroll
    for (int i = 0; i < 3; i++) {
        g_M[n][i * 4 + 0] = s * R[i][0];
        g_M[n][i * 4 + 1] = s * R[i][1];
        g_M[n][i * 4 + 2] = s * R[i][2];
        g_M[n][i * 4 + 3] =
            32.0f * (t[i] * inv_m - (R[i][0] + R[i][1] + R[i][2])) + 31.5f;
    }
}

// blockIdx.z in [0,64): warp tiles (8 z-tiles x 8 pairs).
// blockIdx.z in [64,72): frame-0 copy blocks (512 of them), overlapping DRAM
// copy with the L1-bound warp work.
__global__ __launch_bounds__(256) void warp_kernel(const float* __restrict__ vox,
                                                   float* __restrict__ out) {
    const int tid = threadIdx.x;

    if (blockIdx.z >= 64) {
        // ---- copy path: out[b,0] = vox[b,0] for b=0,1
        int cb = ((int)blockIdx.z - 64) * 64 + (int)blockIdx.y * 8 + (int)blockIdx.x;
        int batch = cb >> 8;                 // 0..1 (256 blocks each)
        int local = cb & 255;
        const float4* s4 = (const float4*)(vox + (size_t)batch * 5 * CVOL);
        float4* d4 = (float4*)(out + (size_t)batch * 5 * CVOL);
        int base = local * 4096 + tid;       // 4096 float4 per block
#pragma unroll
        for (int i = 0; i < 16; i++)
            d4[base + i * 256] = s4[base + i * 256];
        return;
    }

    const int n = blockIdx.z >> 3;  // pair 0..7

    __shared__ float Ms[12];
    __shared__ int sO[3], sD[3];
    __shared__ int sSkip;
    __shared__ __align__(16) float tile[TILE_FLOATS];

    if (tid < 12) Ms[tid] = g_M[n][tid];
    __syncthreads();

    const int bx0 = (int)blockIdx.x * 8;
    const int by0 = (int)blockIdx.y * 8;
    const int bz0 = (int)(blockIdx.z & 7) * 8;

    if (tid == 0) {
        int skip = 0;
#pragma unroll
        for (int i = 0; i < 3; i++) {
            float a = Ms[i * 4 + 0], b = Ms[i * 4 + 1], c = Ms[i * 4 + 2], d = Ms[i * 4 + 3];
            float xl = (float)bx0, xh = (float)(bx0 + 7);
            float yl = (float)by0, yh = (float)(by0 + 7);
            float zl = (float)bz0, zh = (float)(bz0 + 7);
            float fmin = d + fminf(a * xl, a * xh) + fminf(b * yl, b * yh) + fminf(c * zl, c * zh);
            float fmax = d + fmaxf(a * xl, a * xh) + fmaxf(b * yl, b * yh) + fmaxf(c * zl, c * zh);
            int o = (int)floorf(fmin);
            int dd = (int)floorf(fmax) + 2 - o;  // covers floor(min)..floor(max)+1 (<=15)
            if (dd > 16) dd = 16;                // safety
            sO[i] = o;
            sD[i] = dd;
            skip |= (o > 63) | (o + dd <= 0);
        }
        sSkip = skip;
    }
    __syncthreads();

    const int b = n >> 2, k = n & 3;
    const int frame = b * 5 + 1 + k;
    const float* __restrict__ src = vox + (size_t)frame * CVOL;
    float* __restrict__ dstf = out + (size_t)frame * CVOL;

    const int lx = bx0 + (tid & 7);
    const int ly = by0 + ((tid >> 3) & 7);
    const int lz = bz0 + (tid >> 6);  // p=0: z, p=1: z+4
    const int dst0 = lz * GG + ly * G + lx;

    if (sSkip) {
#pragma unroll
        for (int c = 0; c < NCH; c++) {
            dstf[dst0 + c * GGG] = 0.0f;
            dstf[dst0 + 4 * GG + c * GGG] = 0.0f;
        }
        return;
    }

    const int ox = sO[0], oy = sO[1], oz = sO[2];
    const int dx = sD[0], dy = sD[1], dz = sD[2];
    const int xfrac = ox & 3;
    const int ox4 = ox - xfrac;            // 4-aligned x window base
    const int nseg = (xfrac + dx + 3) >> 2; // <= 5 float4 segments per row

    // ---- per-point weights & smem base offsets (computed ONCE, reused over 16 ch)
    float w[2][8];
    int soff[2];
#pragma unroll
    for (int p = 0; p < 2; p++) {
        float xf = (float)lx, yf = (float)ly, zf = (float)(lz + p * 4);
        float fx = fmaf(Ms[2], zf, fmaf(Ms[1], yf, fmaf(Ms[0], xf, Ms[3])));
        float fy = fmaf(Ms[6], zf, fmaf(Ms[5], yf, fmaf(Ms[4], xf, Ms[7])));
        float fz = fmaf(Ms[10], zf, fmaf(Ms[9], yf, fmaf(Ms[8], xf, Ms[11])));
        float xfl = floorf(fx), yfl = floorf(fy), zfl = floorf(fz);
        float tx = fx - xfl, ty = fy - yfl, tz = fz - zfl;
        int ix0 = (int)xfl, iy0 = (int)yfl, iz0 = (int)zfl;

        float wx0 = ((unsigned)ix0 < 64u) ? (1.0f - tx) : 0.0f;
        float wx1 = ((unsigned)(ix0 + 1) < 64u) ? tx : 0.0f;
        float wy0 = ((unsigned)iy0 < 64u) ? (1.0f - ty) : 0.0f;
        float wy1 = ((unsigned)(iy0 + 1) < 64u) ? ty : 0.0f;
        float wz0 = ((unsigned)iz0 < 64u) ? (1.0f - tz) : 0.0f;
        float wz1 = ((unsigned)(iz0 + 1) < 64u) ? tz : 0.0f;

        float wz0y0 = wz0 * wy0, wz0y1 = wz0 * wy1;
        float wz1y0 = wz1 * wy0, wz1y1 = wz1 * wy1;
        w[p][0] = wz0y0 * wx0; w[p][1] = wz0y0 * wx1;
        w[p][2] = wz0y1 * wx0; w[p][3] = wz0y1 * wx1;
        w[p][4] = wz1y0 * wx0; w[p][5] = wz1y0 * wx1;
        w[p][6] = wz1y1 * wx0; w[p][7] = wz1y1 * wx1;

        soff[p] = (iz0 - oz) * ZSTRIDE + (iy0 - oy) * XPITCH + (ix0 - ox4);
    }

    // ---- precompute staging addresses (channel-invariant): dz*dy rows x nseg f4
    // Segments 4-aligned in x: fully in-range-x or fully OOB-x (zero weight).
    // Clamp y,z to [0,63] and linear offset to [0, GGG-4] for address safety
    // (all candidates are multiples of 4, preserving 16B alignment).
    int lin[5], sof[5];
    bool act[5];
    const int rowlen = dy * nseg;
    const int total = dz * rowlen;
#pragma unroll
    for (int i = 0; i < 5; i++) {
        int idx = tid + i * 256;
        act[i] = idx < total;
        int zi = idx / rowlen;
        int r = idx - zi * rowlen;
        int yi = r / nseg;
        int s = r - yi * nseg;
        int zc = min(max(oz + zi, 0), 63);
        int yc = min(max(oy + yi, 0), 63);
        int l = zc * GG + yc * G + (ox4 + 4 * s);
        lin[i] = min(max(l, 0), GGG - 4);
        sof[i] = zi * ZSTRIDE + yi * XPITCH + 4 * s;
    }

#pragma unroll 1
    for (int c = 0; c < NCH; c++) {
        const float* __restrict__ sc = src + c * GGG;
        __syncthreads();  // previous channel's readers done
#pragma unroll
        for (int i = 0; i < 5; i++) {
            if (act[i]) {
                float4 v = __ldg((const float4*)(sc + lin[i]));
                *(float4*)&tile[sof[i]] = v;
            }
        }
        __syncthreads();

#pragma unroll
        for (int p = 0; p < 2; p++) {
            const int s = soff[p];
            float acc = w[p][0] * tile[s];
            acc = fmaf(w[p][1], tile[s + 1], acc);
            acc = fmaf(w[p][2], tile[s + XPITCH], acc);
            acc = fmaf(w[p][3], tile[s + XPITCH + 1], acc);
            acc = fmaf(w[p][4], tile[s + ZSTRIDE], acc);
            acc = fmaf(w[p][5], tile[s + ZSTRIDE + 1], acc);
            acc = fmaf(w[p][6], tile[s + ZSTRIDE + XPITCH], acc);
            acc = fmaf(w[p][7], tile[s + ZSTRIDE + XPITCH + 1], acc);
            dstf[dst0 + p * (4 * GG) + c * GGG] = acc;
        }
    }
}

extern "C" void kernel_launch(void* const* d_in, const int* in_sizes, int n_in,
                              void* d_out, int out_size) {
    const float* vox   = (const float*)d_in[0];   // (2,5,16,64,64,64) fp32
    const float* poses = (const float*)d_in[1];   // (2,5,4,4) fp32
    float* out = (float*)d_out;

    xform_kernel<<<1, 32>>>(poses);

    // z: 64 warp-tile slices (8 z-tiles x 8 pairs) + 8 copy slices (512 copy blocks)
    dim3 block(256, 1, 1);
    dim3 grid(8, 8, 72);
    warp_kernel<<<grid, block>>>(vox, out);
}